// round 1
// baseline (speedup 1.0000x reference)
#include <cuda_runtime.h>
#include <math.h>
#include <stdint.h>

// ---------------- constants ----------------
#define N_PIX (480*640)
#define NM    (480*480)          // one 480x480 plane
#define N1    (8*20*480*480)     // one full (bs,20,480,480) tensor
#define VOXN  65280000           // 8*100*100*48*17

// ---------------- device scratch (no allocations allowed) ----------------
__device__ float g_vox[VOXN];                 // [b][x][y][z][ch]  261MB
__device__ float g_proj[8*19*100*100];        // [b][plane][y][x]  planes: 0=map 1=exp 2..17=sem 18=stair
__device__ float g_rot[35020800];             // [b][plane][i][j]  8*19*480*480  140MB
__device__ float g_stair[8*480*480];          // translated stair ch0 (unmasked)
__device__ float g_par[32];                   // per b: cos, sin, stx, sty
__device__ int   g_sxy[2];                    // stair circle center (x, y), from batch 0

// ---------------- K0: poses + transform params ----------------
__global__ void k_pose(const float* __restrict__ pose_obs,
                       const float* __restrict__ poses_last,
                       float* __restrict__ out_pose) {
    int b = threadIdx.x;
    if (b >= 8) return;
    const float DEGf = 57.29577951308232f;
    float tr = poses_last[b*3+2] / DEGf;
    float s = sinf(tr), c = cosf(tr);
    float ny = poses_last[b*3+1] + pose_obs[b*3+0]*s + pose_obs[b*3+1]*c;
    float nx = poses_last[b*3+0] + pose_obs[b*3+0]*c - pose_obs[b*3+1]*s;
    float no = poses_last[b*3+2] + pose_obs[b*3+2]*DEGf;
    no = fmodf(no - 180.0f, 360.0f) + 180.0f;
    no = fmodf(no + 180.0f, 360.0f) - 180.0f;
    out_pose[b*3+0] = nx; out_pose[b*3+1] = ny; out_pose[b*3+2] = no;

    float stx = -(nx*100.0f/5.0f - 240.0f)/240.0f;
    float sty = -(ny*100.0f/5.0f - 240.0f)/240.0f;
    float st_t = (90.0f - no) * 0.017453292519943295f;
    g_par[b*4+0] = cosf(st_t);
    g_par[b*4+1] = sinf(st_t);
    g_par[b*4+2] = stx;
    g_par[b*4+3] = sty;
    if (b == 0) {
        int sy = (int)(ny*100.0f/5.0f); sy = min(max(sy,30),449);
        int sx = (int)(nx*100.0f/5.0f); sx = min(max(sx,30),449);
        g_sxy[0] = sx; g_sxy[1] = sy;
    }
}

// ---------------- K1: zero voxel grid ----------------
__global__ void k_zero() {
    size_t i = (size_t)blockIdx.x*blockDim.x + threadIdx.x;
    if (i < VOXN/4) ((float4*)g_vox)[i] = make_float4(0.f,0.f,0.f,0.f);
}

// ---------------- K2: trilinear splat ----------------
__global__ void k_splat(const float* __restrict__ obs,
                        const float* __restrict__ eve, float camf) {
    int t = blockIdx.x*blockDim.x + threadIdx.x;
    if (t >= 8*240*320) return;
    int j = t % 320;
    int i = (t/320) % 240;
    int b = t / (320*240);
    const float* ob = obs + (size_t)b*20*N_PIX;

    float d = ob[(size_t)3*N_PIX + (size_t)(2*i)*640 + 2*j];
    float X = ((float)(2*j) - 319.5f) * d / camf;
    float Z = ((float)(479 - 2*i) - 239.5f) * d / camf;
    float th = eve[b] * 0.017453292519943295f;
    float ct = cosf(th), st = sinf(th);
    float Yr = ct*d - st*Z;
    float Zr = st*d + ct*Z + 88.0f;
    float Xs = X + 250.0f;
    float cx = (Xs/5.0f - 50.0f)/100.0f*2.0f;
    float cy = (Yr/5.0f - 50.0f)/100.0f*2.0f;
    float cz = (Zr/5.0f - 16.0f)/48.0f*2.0f;
    float pos[3] = { cx*50.0f+50.0f, cy*50.0f+50.0f, cz*24.0f+24.0f };
    const int gd[3] = {100,100,48};

    int   ip[3][2];
    float w [3][2];
    #pragma unroll
    for (int dd=0; dd<3; dd++) {
        float fl = floorf(pos[dd]);
        #pragma unroll
        for (int ix=0; ix<2; ix++) {
            float pix = fl + (float)ix;
            bool safe = (pix > 0.0f) && (pix < (float)gd[dd]);
            w[dd][ix]  = safe ? (1.0f - fabsf(pos[dd]-pix)) : 0.0f;
            ip[dd][ix] = safe ? (int)pix : 0;
        }
    }

    float fs[16];
    #pragma unroll
    for (int c=0;c<16;c++) {
        const float* p = ob + (size_t)(4+c)*N_PIX + (size_t)(2*i)*640 + 2*j;
        fs[c] = (p[0] + p[1] + p[640] + p[641]) * 0.25f;
    }

    #pragma unroll
    for (int a=0;a<2;a++)
    #pragma unroll
    for (int e=0;e<2;e++) {
        float w01 = w[0][a]*w[1][e];
        if (w01 == 0.0f) continue;
        #pragma unroll
        for (int f=0;f<2;f++) {
            float ww = w01*w[2][f];
            if (ww == 0.0f) continue;
            size_t base = ((((size_t)b*100 + ip[0][a])*100 + ip[1][e])*48 + ip[2][f])*17;
            atomicAdd(&g_vox[base], ww);
            #pragma unroll
            for (int c=0;c<16;c++) atomicAdd(&g_vox[base+1+c], fs[c]*ww);
        }
    }
}

// ---------------- K3: round + z projections -> 19 planes ----------------
__global__ void k_proj() {
    int t = blockIdx.x*blockDim.x + threadIdx.x;
    if (t >= 8*100*100*17) return;
    int ch = t % 17;
    int y  = (t/17) % 100;
    int x  = (t/1700) % 100;
    int b  = t / 170000;
    const float* v = g_vox + ((((size_t)b*100 + x)*100 + y)*48)*17 + ch;
    float ah=0.f, allv=0.f, stv=0.f;
    #pragma unroll
    for (int z=0; z<48; z++) {
        float q = rintf(v[(size_t)z*17]);
        allv += q;
        if (z>=13 && z<35) ah += q;
        if (z>=20 && z<25) stv += q;
    }
    size_t po = (size_t)b*19*10000 + (size_t)y*100 + x;
    if (ch == 0) {
        g_proj[po]            = fminf(fmaxf(ah,  0.f),1.f);  // fp_map
        g_proj[po +  10000]   = fminf(fmaxf(allv,0.f),1.f);  // fp_exp
        g_proj[po + 18*10000] = fminf(fmaxf(stv, 0.f),1.f);  // fp_stair
    } else {
        g_proj[po + (size_t)(1+ch)*10000] = fminf(fmaxf(ah/5.0f,0.f),1.f); // sem
    }
}

// ---------------- K4: rotation grid_sample ----------------
__global__ void k_rot() {
    int t = blockIdx.x*blockDim.x + threadIdx.x;
    if (t >= 8*480*480) return;
    int j = t % 480, i = (t/480)%480, b = t/(480*480);
    float c = g_par[b*4+0], s = g_par[b*4+1];
    float gx = ((float)j + 0.5f)*2.0f/480.0f - 1.0f;
    float gy = ((float)i + 0.5f)*2.0f/480.0f - 1.0f;
    float gxr = c*gx - s*gy;
    float gyr = s*gx + c*gy;
    float fx = (gxr + 1.0f)*479.0f/2.0f;
    float fy = (gyr + 1.0f)*479.0f/2.0f;
    float x0f = floorf(fx), y0f = floorf(fy);
    int x0 = (int)x0f, y0 = (int)y0f;
    size_t ob = ((size_t)b*19*480 + i)*480 + j;

    if (x0 < 189 || x0 > 289 || y0 < 239 || y0 > 339) {
        #pragma unroll
        for (int p=0;p<19;p++) g_rot[ob + (size_t)p*NM] = 0.0f;
        return;
    }
    float wx1 = fx - x0f, wx0 = 1.0f - wx1;
    float wy1 = fy - y0f, wy0 = 1.0f - wy1;
    float w00 = wx0*wy0, w10 = wx1*wy0, w01 = wx0*wy1, w11 = wx1*wy1;

    int xs0 = x0-190, xs1 = x0-189, ys0 = y0-240, ys1 = y0-239;
    bool vx0 = (xs0>=0 && xs0<100), vx1 = (xs1>=0 && xs1<100);
    bool vy0 = (ys0>=0 && ys0<100), vy1 = (ys1>=0 && ys1<100);
    bool v00 = vx0&&vy0, v10 = vx1&&vy0, v01 = vx0&&vy1, v11 = vx1&&vy1;
    int o00 = ys0*100+xs0, o10 = ys0*100+xs1, o01 = ys1*100+xs0, o11 = ys1*100+xs1;
    const float* pb = g_proj + (size_t)b*19*10000;
    #pragma unroll
    for (int p=0;p<19;p++) {
        const float* pp = pb + p*10000;
        float a  = v00 ? pp[o00] : 0.f;
        float bb = v10 ? pp[o10] : 0.f;
        float cc = v01 ? pp[o01] : 0.f;
        float dd = v11 ? pp[o11] : 0.f;
        g_rot[ob + (size_t)p*NM] = a*w00 + bb*w10 + cc*w01 + dd*w11;
    }
}

// ---------------- K5: translation grid_sample -> translated + stair scratch ----------------
__global__ void k_trans(float* __restrict__ out) {
    int t = blockIdx.x*blockDim.x + threadIdx.x;
    if (t >= 8*480*480) return;
    int j = t % 480, i = (t/480)%480, b = t/(480*480);
    float stx = g_par[b*4+2], sty = g_par[b*4+3];
    float gx = ((float)j + 0.5f)*2.0f/480.0f - 1.0f + stx;
    float gy = ((float)i + 0.5f)*2.0f/480.0f - 1.0f + sty;
    float fx = (gx + 1.0f)*479.0f/2.0f;
    float fy = (gy + 1.0f)*479.0f/2.0f;
    float x0f = floorf(fx), y0f = floorf(fy);
    int x0 = (int)x0f, y0 = (int)y0f;
    float wx1 = fx - x0f, wx0 = 1.0f - wx1;
    float wy1 = fy - y0f, wy0 = 1.0f - wy1;
    float w00 = wx0*wy0, w10 = wx1*wy0, w01 = wx0*wy1, w11 = wx1*wy1;

    bool vx0 = (x0  >=0 && x0  <480), vx1 = (x0+1>=0 && x0+1<480);
    bool vy0 = (y0  >=0 && y0  <480), vy1 = (y0+1>=0 && y0+1<480);
    bool v00 = vx0&&vy0, v10 = vx1&&vy0, v01 = vx0&&vy1, v11 = vx1&&vy1;
    int o00 = y0*480+x0, o10 = y0*480+x0+1, o01 = (y0+1)*480+x0, o11 = (y0+1)*480+x0+1;
    const float* rb = g_rot + (size_t)b*19*NM;

    size_t tb0 = ((size_t)b*20*480 + i)*480 + j;
    #pragma unroll
    for (int p=0;p<19;p++) {
        const float* pp = rb + (size_t)p*NM;
        float a  = v00 ? pp[o00] : 0.f;
        float bb = v10 ? pp[o10] : 0.f;
        float cc = v01 ? pp[o01] : 0.f;
        float dd = v11 ? pp[o11] : 0.f;
        float r = a*w00 + bb*w10 + cc*w01 + dd*w11;
        if (p == 0)      out[tb0]                 = r;
        else if (p == 1) out[tb0 + (size_t)NM]    = r;
        else if (p <= 17) out[tb0 + (size_t)(p+2)*NM] = r;
        else g_stair[(size_t)b*NM + (size_t)i*480 + j] = r;
    }
    out[tb0 + (size_t)2*NM] = 0.0f;   // channels 2,3 of agent_view are always zero
    out[tb0 + (size_t)3*NM] = 0.0f;
}

// ---------------- K6: maxpool/diff/mask/max-merge -> map_pred, map_pred_stair ----------------
__global__ void k_final(const float* __restrict__ maps_last,
                        const float* __restrict__ eve,
                        const float* __restrict__ out_t,
                        float* __restrict__ out_p,
                        float* __restrict__ out_s) {
    int t = blockIdx.x*blockDim.x + threadIdx.x;
    if (t >= 8*480*480) return;
    int j = t % 480, i = (t/480)%480, b = t/(480*480);
    size_t pix = (size_t)i*480 + j;
    const float* tb = out_t + (size_t)b*20*NM;

    // maxpool3 on translated ch0
    float mp = -INFINITY;
    #pragma unroll
    for (int di=-1; di<=1; di++) {
        int ii = i + di;
        if (ii < 0 || ii >= 480) continue;
        #pragma unroll
        for (int dj=-1; dj<=1; dj++) {
            int jj = j + dj;
            if (jj < 0 || jj >= 480) continue;
            mp = fmaxf(mp, tb[(size_t)ii*480 + jj]);
        }
    }
    float t0 = tb[pix];
    float t1 = tb[(size_t)NM + pix];
    bool eve0 = (eve[b] == 0.0f);
    bool dth  = (t1 - mp) > 0.8f;

    float mask = 1.0f;
    if (b == 0) {
        float dy = (float)i - (float)g_sxy[1] + 0.5f;
        float dx = (float)j - (float)g_sxy[0] + 0.5f;
        mask = (dy*dy + dx*dx <= 900.0f) ? 1.0f : 0.0f;
    }
    float ts0 = g_stair[(size_t)b*NM + pix] * mask;   // mask==1 for b!=0
    float ts1 = (b == 0) ? t1 * mask : t1;
    bool dsth = (ts1 - ts0) > 0.8f;

    const float* ml = maps_last + (size_t)b*20*NM;
    size_t ob = (size_t)b*20*NM + pix;
    #pragma unroll
    for (int c=0; c<20; c++) {
        float mlv = ml[(size_t)c*NM + pix];
        float tc;
        if (c == 0) tc = t0;
        else if (c == 1) tc = t1;
        else if (c < 4) tc = 0.0f;
        else tc = tb[(size_t)c*NM + pix];
        float m2 = fmaxf(mlv, tc);
        out_p[ob + (size_t)c*NM] = (c==0 && eve0 && dth) ? 0.0f : m2;

        float m3;
        if (c == 0)      m3 = (eve0 && dsth) ? 0.0f : fmaxf(mlv, ts0);
        else if (c == 1) m3 = fmaxf(mlv, ts1);
        else             m3 = m2;
        out_s[ob + (size_t)c*NM] = m3;
    }
}

// ---------------- launch ----------------
extern "C" void kernel_launch(void* const* d_in, const int* in_sizes, int n_in,
                              void* d_out, int out_size) {
    const float* obs        = (const float*)d_in[0];
    const float* pose_obs   = (const float*)d_in[1];
    const float* maps_last  = (const float*)d_in[2];
    const float* poses_last = (const float*)d_in[3];
    const float* eve        = (const float*)d_in[4];
    float* out = (float*)d_out;

    float camf = (float)(320.0 / tan(39.5 * 3.14159265358979323846 / 180.0));

    k_pose <<<1, 8>>>(pose_obs, poses_last, out + (size_t)3*N1);
    k_zero <<<(VOXN/4 + 255)/256, 256>>>();
    k_splat<<<(8*240*320 + 255)/256, 256>>>(obs, eve, camf);
    k_proj <<<(8*100*100*17 + 255)/256, 256>>>();
    k_rot  <<<(8*480*480 + 255)/256, 256>>>();
    k_trans<<<(8*480*480 + 255)/256, 256>>>(out);
    k_final<<<(8*480*480 + 255)/256, 256>>>(maps_last, eve, out,
                                            out + (size_t)N1, out + (size_t)2*N1);
}

// round 2
// speedup vs baseline: 1.5962x; 1.5962x over previous
#include <cuda_runtime.h>
#include <math.h>
#include <stdint.h>

// ---------------- constants ----------------
#define N_PIX (480*640)
#define NM    (480*480)          // one 480x480 plane
#define N1    (8*20*480*480)     // one full (bs,20,480,480) tensor
#define CHP   20                 // padded channels per voxel (16B-aligned groups)
#define VOXN  (8*100*100*48*CHP) // 76.8M floats

// ---------------- device scratch ----------------
__device__ float g_vox[VOXN];                 // [b][x][y][z][chp]  307MB, kept zeroed between launches
__device__ float g_proj[8*19*100*100];        // [b][plane][y][x]; 0=map 1=exp 2..17=sem 18=stair
__device__ float g_par[32];                   // per b: cos, sin, stx, sty
__device__ int   g_sxy[2];                    // stair circle center (x, y), batch 0

// ---------------- vector reduction helper ----------------
__device__ __forceinline__ void red4(float* p, float a, float b, float c, float d) {
    asm volatile("red.global.add.v4.f32 [%0], {%1,%2,%3,%4};"
                 :: "l"(p), "f"(a), "f"(b), "f"(c), "f"(d) : "memory");
}

// ---------------- K0: poses + transform params ----------------
__global__ void k_pose(const float* __restrict__ pose_obs,
                       const float* __restrict__ poses_last,
                       float* __restrict__ out_pose) {
    int b = threadIdx.x;
    if (b >= 8) return;
    const float DEGf = 57.29577951308232f;
    float tr = poses_last[b*3+2] / DEGf;
    float s = sinf(tr), c = cosf(tr);
    float ny = poses_last[b*3+1] + pose_obs[b*3+0]*s + pose_obs[b*3+1]*c;
    float nx = poses_last[b*3+0] + pose_obs[b*3+0]*c - pose_obs[b*3+1]*s;
    float no = poses_last[b*3+2] + pose_obs[b*3+2]*DEGf;
    no = fmodf(no - 180.0f, 360.0f) + 180.0f;
    no = fmodf(no + 180.0f, 360.0f) - 180.0f;
    out_pose[b*3+0] = nx; out_pose[b*3+1] = ny; out_pose[b*3+2] = no;

    float stx = -(nx*100.0f/5.0f - 240.0f)/240.0f;
    float sty = -(ny*100.0f/5.0f - 240.0f)/240.0f;
    float st_t = (90.0f - no) * 0.017453292519943295f;
    g_par[b*4+0] = cosf(st_t);
    g_par[b*4+1] = sinf(st_t);
    g_par[b*4+2] = stx;
    g_par[b*4+3] = sty;
    if (b == 0) {
        int sy = (int)(ny*100.0f/5.0f); sy = min(max(sy,30),449);
        int sx = (int)(nx*100.0f/5.0f); sx = min(max(sx,30),449);
        g_sxy[0] = sx; g_sxy[1] = sy;
    }
}

// ---------------- K1: trilinear splat (vector red) ----------------
__global__ void k_splat(const float* __restrict__ obs,
                        const float* __restrict__ eve, float camf) {
    int t = blockIdx.x*blockDim.x + threadIdx.x;
    if (t >= 8*240*320) return;
    int j = t % 320;
    int i = (t/320) % 240;
    int b = t / (320*240);
    const float* ob = obs + (size_t)b*20*N_PIX;

    float d = ob[(size_t)3*N_PIX + (size_t)(2*i)*640 + 2*j];
    float X = ((float)(2*j) - 319.5f) * d / camf;
    float Z = ((float)(479 - 2*i) - 239.5f) * d / camf;
    float th = eve[b] * 0.017453292519943295f;
    float ct = cosf(th), st = sinf(th);
    float Yr = ct*d - st*Z;
    float Zr = st*d + ct*Z + 88.0f;
    float Xs = X + 250.0f;
    float cx = (Xs/5.0f - 50.0f)/100.0f*2.0f;
    float cy = (Yr/5.0f - 50.0f)/100.0f*2.0f;
    float cz = (Zr/5.0f - 16.0f)/48.0f*2.0f;
    float pos[3] = { cx*50.0f+50.0f, cy*50.0f+50.0f, cz*24.0f+24.0f };
    const int gd[3] = {100,100,48};

    int   ip[3][2];
    float w [3][2];
    #pragma unroll
    for (int dd=0; dd<3; dd++) {
        float fl = floorf(pos[dd]);
        #pragma unroll
        for (int ix=0; ix<2; ix++) {
            float pix = fl + (float)ix;
            bool safe = (pix > 0.0f) && (pix < (float)gd[dd]);
            w[dd][ix]  = safe ? (1.0f - fabsf(pos[dd]-pix)) : 0.0f;
            ip[dd][ix] = safe ? (int)pix : 0;
        }
    }

    float fs[16];
    #pragma unroll
    for (int c=0;c<16;c++) {
        const float* p = ob + (size_t)(4+c)*N_PIX + (size_t)(2*i)*640 + 2*j;
        fs[c] = (p[0] + p[1] + p[640] + p[641]) * 0.25f;
    }

    #pragma unroll
    for (int a=0;a<2;a++)
    #pragma unroll
    for (int e=0;e<2;e++) {
        float w01 = w[0][a]*w[1][e];
        if (w01 == 0.0f) continue;
        #pragma unroll
        for (int f=0;f<2;f++) {
            float ww = w01*w[2][f];
            if (ww == 0.0f) continue;
            float* p = g_vox + ((((size_t)b*100 + ip[0][a])*100 + ip[1][e])*48 + ip[2][f])*CHP;
            red4(p,    ww,        fs[0]*ww,  fs[1]*ww,  fs[2]*ww);
            red4(p+4,  fs[3]*ww,  fs[4]*ww,  fs[5]*ww,  fs[6]*ww);
            red4(p+8,  fs[7]*ww,  fs[8]*ww,  fs[9]*ww,  fs[10]*ww);
            red4(p+12, fs[11]*ww, fs[12]*ww, fs[13]*ww, fs[14]*ww);
            atomicAdd(p+16, fs[15]*ww);
        }
    }
}

// ---------------- K2: round + z projections -> 19 planes, re-zero voxels ----------------
__global__ void k_proj() {
    int t = blockIdx.x*blockDim.x + threadIdx.x;
    if (t >= 8*100*100*17) return;
    int ch = t % 17;
    int y  = (t/17) % 100;
    int x  = (t/1700) % 100;
    int b  = t / 170000;
    float* v = g_vox + ((((size_t)b*100 + x)*100 + y)*48)*CHP + ch;
    float ah=0.f, allv=0.f, stv=0.f;
    #pragma unroll
    for (int z=0; z<48; z++) {
        float* a = v + (size_t)z*CHP;
        float q = rintf(*a);
        *a = 0.0f;                       // fused re-zero for the next launch
        allv += q;
        if (z>=13 && z<35) ah += q;
        if (z>=20 && z<25) stv += q;
    }
    size_t po = (size_t)b*19*10000 + (size_t)y*100 + x;
    if (ch == 0) {
        g_proj[po]            = fminf(fmaxf(ah,  0.f),1.f);  // fp_map
        g_proj[po +  10000]   = fminf(fmaxf(allv,0.f),1.f);  // fp_exp
        g_proj[po + 18*10000] = fminf(fmaxf(stv, 0.f),1.f);  // fp_stair
    } else {
        g_proj[po + (size_t)(1+ch)*10000] = fminf(fmaxf(ah/5.0f,0.f),1.f); // sem
    }
}

// ---------------- fused rot-sample helpers ----------------
struct Tap { int o0,o1,o2,o3; float w0,w1,w2,w3; };

// taps into g_proj for rotated-image pixel (ir, jr); returns false if value is 0
__device__ __forceinline__ bool rot_taps(float cc, float ss, int ir, int jr, Tap& tp) {
    if (ir < 0 || ir >= 480 || jr < 0 || jr >= 480) return false;
    float gxp = ((float)jr + 0.5f)*(1.0f/240.0f) - 1.0f;
    float gyp = ((float)ir + 0.5f)*(1.0f/240.0f) - 1.0f;
    float fxp = (cc*gxp - ss*gyp + 1.0f)*239.5f;
    float fyp = (ss*gxp + cc*gyp + 1.0f)*239.5f;
    float xf = floorf(fxp), yf = floorf(fyp);
    int xp = (int)xf, yp = (int)yf;
    if (xp < 189 || xp > 289 || yp < 239 || yp > 339) return false;
    float ux1 = fxp - xf, ux0 = 1.0f - ux1;
    float uy1 = fyp - yf, uy0 = 1.0f - uy1;
    int xs0 = xp-190, xs1 = xp-189, ys0 = yp-240, ys1 = yp-239;
    bool vx0 = (xs0>=0 && xs0<100), vx1 = (xs1>=0 && xs1<100);
    bool vy0 = (ys0>=0 && ys0<100), vy1 = (ys1>=0 && ys1<100);
    tp.w0 = (vx0&&vy0) ? ux0*uy0 : 0.0f;
    tp.w1 = (vx1&&vy0) ? ux1*uy0 : 0.0f;
    tp.w2 = (vx0&&vy1) ? ux0*uy1 : 0.0f;
    tp.w3 = (vx1&&vy1) ? ux1*uy1 : 0.0f;
    tp.o0 = (vx0&&vy0) ? ys0*100+xs0 : 0;
    tp.o1 = (vx1&&vy0) ? ys0*100+xs1 : 0;
    tp.o2 = (vx0&&vy1) ? ys1*100+xs0 : 0;
    tp.o3 = (vx1&&vy1) ? ys1*100+xs1 : 0;
    return true;
}

// full double-bilinear value of plane 0 ("translated" ch0) at output pixel (in_i, in_j)
__device__ __forceinline__ float trans_val0(const float* pb, float cc, float ss,
                                            float stx, float sty, int in_i, int in_j) {
    float gx = ((float)in_j + 0.5f)*(1.0f/240.0f) - 1.0f + stx;
    float gy = ((float)in_i + 0.5f)*(1.0f/240.0f) - 1.0f + sty;
    float fx = (gx + 1.0f)*239.5f;
    float fy = (gy + 1.0f)*239.5f;
    float x0f = floorf(fx), y0f = floorf(fy);
    int x0 = (int)x0f, y0 = (int)y0f;
    float wx1 = fx - x0f, wx0 = 1.0f - wx1;
    float wy1 = fy - y0f, wy0 = 1.0f - wy1;
    float cw[4] = { wx0*wy0, wx1*wy0, wx0*wy1, wx1*wy1 };
    int  yi[4] = { y0, y0, y0+1, y0+1 };
    int  xi[4] = { x0, x0+1, x0, x0+1 };
    float acc = 0.0f;
    #pragma unroll
    for (int k=0;k<4;k++) {
        Tap tp;
        if (rot_taps(cc, ss, yi[k], xi[k], tp))
            acc += cw[k]*(tp.w0*pb[tp.o0] + tp.w1*pb[tp.o1] + tp.w2*pb[tp.o2] + tp.w3*pb[tp.o3]);
    }
    return acc;
}

// ---------------- K3: fused rot+trans+maxpool+diff+mask+merge ----------------
__global__ void k_post(const float* __restrict__ maps_last,
                       const float* __restrict__ eve,
                       float* __restrict__ out_t,
                       float* __restrict__ out_p,
                       float* __restrict__ out_s) {
    int t = blockIdx.x*blockDim.x + threadIdx.x;
    if (t >= 8*NM) return;
    int j = t % 480, i = (t/480) % 480, b = t/NM;
    float cc  = g_par[b*4+0], ss  = g_par[b*4+1];
    float stx = g_par[b*4+2], sty = g_par[b*4+3];

    float gx = ((float)j + 0.5f)*(1.0f/240.0f) - 1.0f + stx;
    float gy = ((float)i + 0.5f)*(1.0f/240.0f) - 1.0f + sty;
    float fx = (gx + 1.0f)*239.5f;
    float fy = (gy + 1.0f)*239.5f;
    float x0f = floorf(fx), y0f = floorf(fy);
    int x0 = (int)x0f, y0 = (int)y0f;
    float wx1 = fx - x0f, wx0 = 1.0f - wx1;
    float wy1 = fy - y0f, wy0 = 1.0f - wy1;

    // 4 rotated-image source pixels of the translation sample
    Tap ct[4]; bool cin[4];
    cin[0] = rot_taps(cc, ss, y0,   x0,   ct[0]);
    cin[1] = rot_taps(cc, ss, y0,   x0+1, ct[1]);
    cin[2] = rot_taps(cc, ss, y0+1, x0,   ct[2]);
    cin[3] = rot_taps(cc, ss, y0+1, x0+1, ct[3]);

    size_t pix = (size_t)i*480 + j;
    const float* ml = maps_last + (size_t)b*20*NM + pix;
    size_t ob = (size_t)b*20*NM + pix;

    if (!(cin[0] | cin[1] | cin[2] | cin[3])) {
        // all-zero translated pixel: diffs can't exceed 0.8, merges are just max(ml, 0)
        #pragma unroll
        for (int c=0;c<20;c++) {
            out_t[ob + (size_t)c*NM] = 0.0f;
            float m = fmaxf(ml[(size_t)c*NM], 0.0f);
            out_p[ob + (size_t)c*NM] = m;
            out_s[ob + (size_t)c*NM] = m;
        }
        return;
    }

    const float* pb = g_proj + (size_t)b*19*10000;
    float cw[4] = { wx0*wy0, wx1*wy0, wx0*wy1, wx1*wy1 };

    float tv[19];
    #pragma unroll
    for (int p=0;p<19;p++) {
        const float* pp = pb + p*10000;
        float acc = 0.0f;
        #pragma unroll
        for (int k=0;k<4;k++) {
            if (!cin[k]) continue;
            acc += cw[k]*(ct[k].w0*pp[ct[k].o0] + ct[k].w1*pp[ct[k].o1] +
                          ct[k].w2*pp[ct[k].o2] + ct[k].w3*pp[ct[k].o3]);
        }
        tv[p] = acc;
    }

    // 3x3 maxpool of translated ch0 (recompute neighbors from scratch)
    float mp = tv[0];
    #pragma unroll
    for (int di=-1; di<=1; di++) {
        int ii = i + di;
        if (ii < 0 || ii >= 480) continue;
        #pragma unroll
        for (int dj=-1; dj<=1; dj++) {
            if (di == 0 && dj == 0) continue;
            int jj = j + dj;
            if (jj < 0 || jj >= 480) continue;
            mp = fmaxf(mp, trans_val0(pb, cc, ss, stx, sty, ii, jj));
        }
    }

    bool eve0 = (eve[b] == 0.0f);
    float t1 = tv[1];
    bool dth = (t1 - mp) > 0.8f;

    float mask = 1.0f;
    if (b == 0) {
        float dy = (float)i - (float)g_sxy[1] + 0.5f;
        float dx = (float)j - (float)g_sxy[0] + 0.5f;
        mask = (dy*dy + dx*dx <= 900.0f) ? 1.0f : 0.0f;
    }
    float ts0 = tv[18]*mask;
    float ts1 = (b == 0) ? t1*mask : t1;
    bool dsth = (ts1 - ts0) > 0.8f;

    #pragma unroll
    for (int c=0; c<20; c++) {
        float mlv = ml[(size_t)c*NM];
        float tc;
        if (c == 0) tc = tv[0];
        else if (c == 1) tc = t1;
        else if (c < 4) tc = 0.0f;
        else tc = tv[c-2];
        float m2 = fmaxf(mlv, tc);
        out_t[ob + (size_t)c*NM] = tc;
        out_p[ob + (size_t)c*NM] = (c==0 && eve0 && dth) ? 0.0f : m2;
        float m3;
        if (c == 0)      m3 = (eve0 && dsth) ? 0.0f : fmaxf(mlv, ts0);
        else if (c == 1) m3 = fmaxf(mlv, ts1);
        else             m3 = m2;
        out_s[ob + (size_t)c*NM] = m3;
    }
}

// ---------------- launch ----------------
extern "C" void kernel_launch(void* const* d_in, const int* in_sizes, int n_in,
                              void* d_out, int out_size) {
    const float* obs        = (const float*)d_in[0];
    const float* pose_obs   = (const float*)d_in[1];
    const float* maps_last  = (const float*)d_in[2];
    const float* poses_last = (const float*)d_in[3];
    const float* eve        = (const float*)d_in[4];
    float* out = (float*)d_out;

    float camf = (float)(320.0 / tan(39.5 * 3.14159265358979323846 / 180.0));

    k_pose <<<1, 8>>>(pose_obs, poses_last, out + (size_t)3*N1);
    k_splat<<<(8*240*320 + 255)/256, 256>>>(obs, eve, camf);
    k_proj <<<(8*100*100*17 + 255)/256, 256>>>();
    k_post <<<(8*NM + 255)/256, 256>>>(maps_last, eve, out,
                                       out + (size_t)N1, out + (size_t)2*N1);
}

// round 3
// speedup vs baseline: 1.8972x; 1.1886x over previous
#include <cuda_runtime.h>
#include <math.h>
#include <stdint.h>

// ---------------- constants ----------------
#define N_PIX (480*640)
#define NM    (480*480)          // one 480x480 plane
#define N1    (8*20*480*480)     // one full (bs,20,480,480) tensor
#define ZALL  48
#define ZLO   13                 // ah range [13,35)
#define ZHI   35
#define ZSEM  22                 // ZHI-ZLO

// ---------------- device scratch ----------------
__device__ float g_vox0[8*100*100*ZALL];        // [b][x][y][z]        15MB (ch0 counts)
__device__ float g_sem [8*100*100*ZSEM*16];     // [b][x][y][zr][ch]  113MB (sem feats)
__device__ float g_proj[8*19*100*100];          // [b][plane][y][x]; 0=map 1=exp 2..17=sem 18=stair
__device__ float g_stair[8*NM];                 // translated stair ch0 (unmasked)
__device__ float g_par[32];                     // per b: cos, sin, stx, sty
__device__ int   g_sxy[2];                      // stair circle center (x, y), batch 0

// ---------------- vector reduction helper ----------------
__device__ __forceinline__ void red4(float* p, float a, float b, float c, float d) {
    asm volatile("red.global.add.v4.f32 [%0], {%1,%2,%3,%4};"
                 :: "l"(p), "f"(a), "f"(b), "f"(c), "f"(d) : "memory");
}

// ---------------- K0: poses + transform params ----------------
__global__ void k_pose(const float* __restrict__ pose_obs,
                       const float* __restrict__ poses_last,
                       float* __restrict__ out_pose) {
    int b = threadIdx.x;
    if (b >= 8) return;
    const float DEGf = 57.29577951308232f;
    float tr = poses_last[b*3+2] / DEGf;
    float s = sinf(tr), c = cosf(tr);
    float ny = poses_last[b*3+1] + pose_obs[b*3+0]*s + pose_obs[b*3+1]*c;
    float nx = poses_last[b*3+0] + pose_obs[b*3+0]*c - pose_obs[b*3+1]*s;
    float no = poses_last[b*3+2] + pose_obs[b*3+2]*DEGf;
    no = fmodf(no - 180.0f, 360.0f) + 180.0f;
    no = fmodf(no + 180.0f, 360.0f) - 180.0f;
    out_pose[b*3+0] = nx; out_pose[b*3+1] = ny; out_pose[b*3+2] = no;

    float stx = -(nx*100.0f/5.0f - 240.0f)/240.0f;
    float sty = -(ny*100.0f/5.0f - 240.0f)/240.0f;
    float st_t = (90.0f - no) * 0.017453292519943295f;
    g_par[b*4+0] = cosf(st_t);
    g_par[b*4+1] = sinf(st_t);
    g_par[b*4+2] = stx;
    g_par[b*4+3] = sty;
    if (b == 0) {
        int sy = (int)(ny*100.0f/5.0f); sy = min(max(sy,30),449);
        int sx = (int)(nx*100.0f/5.0f); sx = min(max(sx,30),449);
        g_sxy[0] = sx; g_sxy[1] = sy;
    }
}

// ---------------- K1: trilinear splat ----------------
__global__ void k_splat(const float* __restrict__ obs,
                        const float* __restrict__ eve, float camf) {
    int t = blockIdx.x*blockDim.x + threadIdx.x;
    if (t >= 8*240*320) return;
    int j = t % 320;
    int i = (t/320) % 240;
    int b = t / (320*240);
    const float* ob = obs + (size_t)b*20*N_PIX;

    float d = ob[(size_t)3*N_PIX + (size_t)(2*i)*640 + 2*j];
    float X = ((float)(2*j) - 319.5f) * d / camf;
    float Z = ((float)(479 - 2*i) - 239.5f) * d / camf;
    float th = eve[b] * 0.017453292519943295f;
    float ct = cosf(th), st = sinf(th);
    float Yr = ct*d - st*Z;
    float Zr = st*d + ct*Z + 88.0f;
    float Xs = X + 250.0f;
    float cx = (Xs/5.0f - 50.0f)/100.0f*2.0f;
    float cy = (Yr/5.0f - 50.0f)/100.0f*2.0f;
    float cz = (Zr/5.0f - 16.0f)/48.0f*2.0f;
    float pos[3] = { cx*50.0f+50.0f, cy*50.0f+50.0f, cz*24.0f+24.0f };
    const int gd[3] = {100,100,48};

    int   ip[3][2];
    float w [3][2];
    #pragma unroll
    for (int dd=0; dd<3; dd++) {
        float fl = floorf(pos[dd]);
        #pragma unroll
        for (int ix=0; ix<2; ix++) {
            float pix = fl + (float)ix;
            bool safe = (pix > 0.0f) && (pix < (float)gd[dd]);
            w[dd][ix]  = safe ? (1.0f - fabsf(pos[dd]-pix)) : 0.0f;
            ip[dd][ix] = safe ? (int)pix : 0;
        }
    }

    float fs[16];
    #pragma unroll
    for (int c=0;c<16;c++) {
        const float* p = ob + (size_t)(4+c)*N_PIX + (size_t)(2*i)*640 + 2*j;
        fs[c] = (p[0] + p[1] + p[640] + p[641]) * 0.25f;
    }

    #pragma unroll
    for (int a=0;a<2;a++)
    #pragma unroll
    for (int e=0;e<2;e++) {
        float w01 = w[0][a]*w[1][e];
        if (w01 == 0.0f) continue;
        size_t cell = ((size_t)b*100 + ip[0][a])*100 + ip[1][e];
        #pragma unroll
        for (int f=0;f<2;f++) {
            float ww = w01*w[2][f];
            if (ww == 0.0f) continue;
            int z = ip[2][f];
            atomicAdd(&g_vox0[cell*ZALL + z], ww);
            if (z >= ZLO && z < ZHI) {
                float* p = g_sem + (cell*ZSEM + (z-ZLO))*16;
                red4(p,    fs[0]*ww,  fs[1]*ww,  fs[2]*ww,  fs[3]*ww);
                red4(p+4,  fs[4]*ww,  fs[5]*ww,  fs[6]*ww,  fs[7]*ww);
                red4(p+8,  fs[8]*ww,  fs[9]*ww,  fs[10]*ww, fs[11]*ww);
                red4(p+12, fs[12]*ww, fs[13]*ww, fs[14]*ww, fs[15]*ww);
            }
        }
    }
}

// ---------------- K2a: ch0 projections (map/exp/stair) + re-zero ----------------
__global__ void k_proj0() {
    int t = blockIdx.x*blockDim.x + threadIdx.x;
    if (t >= 8*100*100) return;
    int y = t % 100;
    int x = (t/100) % 100;
    int b = t / 10000;
    float4* v = (float4*)(g_vox0 + (size_t)t*ZALL);
    float ah=0.f, allv=0.f, stv=0.f;
    #pragma unroll
    for (int q=0; q<12; q++) {
        float4 r = v[q];
        v[q] = make_float4(0.f,0.f,0.f,0.f);
        float vals[4] = {r.x, r.y, r.z, r.w};
        #pragma unroll
        for (int k=0;k<4;k++) {
            int z = q*4 + k;
            float qq = rintf(vals[k]);
            allv += qq;
            if (z>=ZLO && z<ZHI) ah += qq;
            if (z>=20 && z<25) stv += qq;
        }
    }
    size_t po = (size_t)b*19*10000 + (size_t)y*100 + x;
    g_proj[po]            = fminf(fmaxf(ah,  0.f),1.f);
    g_proj[po +  10000]   = fminf(fmaxf(allv,0.f),1.f);
    g_proj[po + 18*10000] = fminf(fmaxf(stv, 0.f),1.f);
}

// ---------------- K2b: sem projections + re-zero ----------------
__global__ void k_projsem() {
    int t = blockIdx.x*blockDim.x + threadIdx.x;
    if (t >= 8*100*100*16) return;
    int ch = t % 16;
    int cell = t / 16;             // b*10000 + x*100 + y
    int y = cell % 100;
    int x = (cell/100) % 100;
    int b = cell / 10000;
    float* v = g_sem + (size_t)cell*ZSEM*16 + ch;
    float ah = 0.f;
    #pragma unroll
    for (int z=0; z<ZSEM; z++) {
        float* a = v + (size_t)z*16;
        ah += rintf(*a);
        *a = 0.0f;
    }
    g_proj[(size_t)b*19*10000 + (size_t)(2+ch)*10000 + (size_t)y*100 + x]
        = fminf(fmaxf(ah/5.0f, 0.f), 1.f);
}

// ---------------- fused rot-sample helper ----------------
struct Tap { int o0,o1,o2,o3; float w0,w1,w2,w3; };

__device__ __forceinline__ bool rot_taps(float cc, float ss, int ir, int jr, Tap& tp) {
    if (ir < 0 || ir >= 480 || jr < 0 || jr >= 480) return false;
    float gxp = ((float)jr + 0.5f)*(1.0f/240.0f) - 1.0f;
    float gyp = ((float)ir + 0.5f)*(1.0f/240.0f) - 1.0f;
    float fxp = (cc*gxp - ss*gyp + 1.0f)*239.5f;
    float fyp = (ss*gxp + cc*gyp + 1.0f)*239.5f;
    float xf = floorf(fxp), yf = floorf(fyp);
    int xp = (int)xf, yp = (int)yf;
    if (xp < 189 || xp > 289 || yp < 239 || yp > 339) return false;
    float ux1 = fxp - xf, ux0 = 1.0f - ux1;
    float uy1 = fyp - yf, uy0 = 1.0f - uy1;
    int xs0 = xp-190, xs1 = xp-189, ys0 = yp-240, ys1 = yp-239;
    bool vx0 = (xs0>=0 && xs0<100), vx1 = (xs1>=0 && xs1<100);
    bool vy0 = (ys0>=0 && ys0<100), vy1 = (ys1>=0 && ys1<100);
    tp.w0 = (vx0&&vy0) ? ux0*uy0 : 0.0f;
    tp.w1 = (vx1&&vy0) ? ux1*uy0 : 0.0f;
    tp.w2 = (vx0&&vy1) ? ux0*uy1 : 0.0f;
    tp.w3 = (vx1&&vy1) ? ux1*uy1 : 0.0f;
    tp.o0 = (vx0&&vy0) ? ys0*100+xs0 : 0;
    tp.o1 = (vx1&&vy0) ? ys0*100+xs1 : 0;
    tp.o2 = (vx0&&vy1) ? ys1*100+xs0 : 0;
    tp.o3 = (vx1&&vy1) ? ys1*100+xs1 : 0;
    return true;
}

// ---------------- K3: double-bilinear warp -> translated (out_t) + stair scratch ----------------
__global__ void k_warp(float* __restrict__ out_t) {
    int t = blockIdx.x*blockDim.x + threadIdx.x;
    if (t >= 8*NM) return;
    int j = t % 480, i = (t/480) % 480, b = t/NM;
    float cc  = g_par[b*4+0], ss  = g_par[b*4+1];
    float stx = g_par[b*4+2], sty = g_par[b*4+3];

    float gx = ((float)j + 0.5f)*(1.0f/240.0f) - 1.0f + stx;
    float gy = ((float)i + 0.5f)*(1.0f/240.0f) - 1.0f + sty;
    float fx = (gx + 1.0f)*239.5f;
    float fy = (gy + 1.0f)*239.5f;
    float x0f = floorf(fx), y0f = floorf(fy);
    int x0 = (int)x0f, y0 = (int)y0f;
    float wx1 = fx - x0f, wx0 = 1.0f - wx1;
    float wy1 = fy - y0f, wy0 = 1.0f - wy1;

    Tap ct[4]; bool cin[4];
    cin[0] = rot_taps(cc, ss, y0,   x0,   ct[0]);
    cin[1] = rot_taps(cc, ss, y0,   x0+1, ct[1]);
    cin[2] = rot_taps(cc, ss, y0+1, x0,   ct[2]);
    cin[3] = rot_taps(cc, ss, y0+1, x0+1, ct[3]);

    size_t pix = (size_t)i*480 + j;
    size_t ob = (size_t)b*20*NM + pix;

    if (!(cin[0] | cin[1] | cin[2] | cin[3])) {
        #pragma unroll
        for (int c=0;c<20;c++) out_t[ob + (size_t)c*NM] = 0.0f;
        g_stair[(size_t)b*NM + pix] = 0.0f;
        return;
    }

    const float* pb = g_proj + (size_t)b*19*10000;
    float cw[4] = { wx0*wy0, wx1*wy0, wx0*wy1, wx1*wy1 };

    #pragma unroll
    for (int p=0;p<19;p++) {
        const float* pp = pb + p*10000;
        float acc = 0.0f;
        #pragma unroll
        for (int k=0;k<4;k++) {
            if (!cin[k]) continue;
            acc += cw[k]*(ct[k].w0*pp[ct[k].o0] + ct[k].w1*pp[ct[k].o1] +
                          ct[k].w2*pp[ct[k].o2] + ct[k].w3*pp[ct[k].o3]);
        }
        if (p == 0)       out_t[ob]                    = acc;
        else if (p == 1)  out_t[ob + (size_t)NM]       = acc;
        else if (p <= 17) out_t[ob + (size_t)(p+2)*NM] = acc;
        else              g_stair[(size_t)b*NM + pix]  = acc;
    }
    out_t[ob + (size_t)2*NM] = 0.0f;
    out_t[ob + (size_t)3*NM] = 0.0f;
}

// ---------------- K4: maxpool/diff/mask/merge -> map_pred, map_pred_stair ----------------
__global__ void k_merge(const float* __restrict__ maps_last,
                        const float* __restrict__ eve,
                        const float* __restrict__ out_t,
                        float* __restrict__ out_p,
                        float* __restrict__ out_s) {
    int t = blockIdx.x*blockDim.x + threadIdx.x;
    if (t >= 8*NM) return;
    int j = t % 480, i = (t/480) % 480, b = t/NM;
    size_t pix = (size_t)i*480 + j;
    const float* tb = out_t + (size_t)b*20*NM;

    // 3x3 maxpool on translated ch0 (reads L2-hot data just written by k_warp)
    float mp = -INFINITY;
    #pragma unroll
    for (int di=-1; di<=1; di++) {
        int ii = i + di;
        if (ii < 0 || ii >= 480) continue;
        #pragma unroll
        for (int dj=-1; dj<=1; dj++) {
            int jj = j + dj;
            if (jj < 0 || jj >= 480) continue;
            mp = fmaxf(mp, tb[(size_t)ii*480 + jj]);
        }
    }
    float t1 = tb[(size_t)NM + pix];
    bool eve0 = (eve[b] == 0.0f);
    bool dth  = (t1 - mp) > 0.8f;

    float mask = 1.0f;
    if (b == 0) {
        float dy = (float)i - (float)g_sxy[1] + 0.5f;
        float dx = (float)j - (float)g_sxy[0] + 0.5f;
        mask = (dy*dy + dx*dx <= 900.0f) ? 1.0f : 0.0f;
    }
    float ts0 = g_stair[(size_t)b*NM + pix] * mask;
    float ts1 = (b == 0) ? t1*mask : t1;
    bool dsth = (ts1 - ts0) > 0.8f;

    const float* ml = maps_last + (size_t)b*20*NM + pix;
    size_t ob = (size_t)b*20*NM + pix;
    #pragma unroll
    for (int c=0; c<20; c++) {
        float mlv = ml[(size_t)c*NM];
        float tc  = tb[(size_t)c*NM + pix];
        float m2 = fmaxf(mlv, tc);
        out_p[ob + (size_t)c*NM] = (c==0 && eve0 && dth) ? 0.0f : m2;
        float m3;
        if (c == 0)      m3 = (eve0 && dsth) ? 0.0f : fmaxf(mlv, ts0);
        else if (c == 1) m3 = fmaxf(mlv, ts1);
        else             m3 = m2;
        out_s[ob + (size_t)c*NM] = m3;
    }
}

// ---------------- launch ----------------
extern "C" void kernel_launch(void* const* d_in, const int* in_sizes, int n_in,
                              void* d_out, int out_size) {
    const float* obs        = (const float*)d_in[0];
    const float* pose_obs   = (const float*)d_in[1];
    const float* maps_last  = (const float*)d_in[2];
    const float* poses_last = (const float*)d_in[3];
    const float* eve        = (const float*)d_in[4];
    float* out = (float*)d_out;

    float camf = (float)(320.0 / tan(39.5 * 3.14159265358979323846 / 180.0));

    k_pose   <<<1, 8>>>(pose_obs, poses_last, out + (size_t)3*N1);
    k_splat  <<<(8*240*320 + 255)/256, 256>>>(obs, eve, camf);
    k_proj0  <<<(8*100*100 + 255)/256, 256>>>();
    k_projsem<<<(8*100*100*16 + 255)/256, 256>>>();
    k_warp   <<<(8*NM + 255)/256, 256>>>(out);
    k_merge  <<<(8*NM + 255)/256, 256>>>(maps_last, eve, out,
                                         out + (size_t)N1, out + (size_t)2*N1);
}

// round 4
// speedup vs baseline: 2.1004x; 1.1071x over previous
#include <cuda_runtime.h>
#include <math.h>
#include <stdint.h>

// ---------------- constants ----------------
#define N_PIX (480*640)
#define NM    (480*480)          // one 480x480 plane
#define N1    (8*20*480*480)     // one full (bs,20,480,480) tensor
#define ZALL  48
#define ZLO   13                 // ah range [13,35)
#define ZHI   35
#define ZSEM  22                 // ZHI-ZLO

// ---------------- device scratch ----------------
__device__ float g_vox0[8*100*100*ZALL];        // [b][x][y][z]        15MB (ch0 counts)
__device__ float g_sem [8*100*100*ZSEM*16];     // [b][x][y][zr][ch]  113MB (sem feats)
__device__ float g_proj[8*19*100*100];          // [b][plane][y][x]; 0=map 1=exp 2..17=sem 18=stair
__device__ float g_stair[8*NM];                 // translated stair ch0 (unmasked)
__device__ float g_par[32];                     // per b: cos, sin, stx, sty
__device__ int   g_sxy[2];                      // stair circle center (x, y), batch 0

// ---------------- vector reduction helper ----------------
__device__ __forceinline__ void red4(float* p, float a, float b, float c, float d) {
    asm volatile("red.global.add.v4.f32 [%0], {%1,%2,%3,%4};"
                 :: "l"(p), "f"(a), "f"(b), "f"(c), "f"(d) : "memory");
}

// ---------------- K0: poses + transform params ----------------
__global__ void k_pose(const float* __restrict__ pose_obs,
                       const float* __restrict__ poses_last,
                       float* __restrict__ out_pose) {
    int b = threadIdx.x;
    if (b >= 8) return;
    const float DEGf = 57.29577951308232f;
    float tr = poses_last[b*3+2] / DEGf;
    float s = sinf(tr), c = cosf(tr);
    float ny = poses_last[b*3+1] + pose_obs[b*3+0]*s + pose_obs[b*3+1]*c;
    float nx = poses_last[b*3+0] + pose_obs[b*3+0]*c - pose_obs[b*3+1]*s;
    float no = poses_last[b*3+2] + pose_obs[b*3+2]*DEGf;
    no = fmodf(no - 180.0f, 360.0f) + 180.0f;
    no = fmodf(no + 180.0f, 360.0f) - 180.0f;
    out_pose[b*3+0] = nx; out_pose[b*3+1] = ny; out_pose[b*3+2] = no;

    float stx = -(nx*100.0f/5.0f - 240.0f)/240.0f;
    float sty = -(ny*100.0f/5.0f - 240.0f)/240.0f;
    float st_t = (90.0f - no) * 0.017453292519943295f;
    g_par[b*4+0] = cosf(st_t);
    g_par[b*4+1] = sinf(st_t);
    g_par[b*4+2] = stx;
    g_par[b*4+3] = sty;
    if (b == 0) {
        int sy = (int)(ny*100.0f/5.0f); sy = min(max(sy,30),449);
        int sx = (int)(nx*100.0f/5.0f); sx = min(max(sx,30),449);
        g_sxy[0] = sx; g_sxy[1] = sy;
    }
}

// ---------------- K1: trilinear splat ----------------
__global__ void k_splat(const float* __restrict__ obs,
                        const float* __restrict__ eve, float camf) {
    int t = blockIdx.x*blockDim.x + threadIdx.x;
    if (t >= 8*240*320) return;
    int j = t % 320;
    int i = (t/320) % 240;
    int b = t / (320*240);
    const float* ob = obs + (size_t)b*20*N_PIX;

    float d = ob[(size_t)3*N_PIX + (size_t)(2*i)*640 + 2*j];
    float X = ((float)(2*j) - 319.5f) * d / camf;
    float Z = ((float)(479 - 2*i) - 239.5f) * d / camf;
    float th = eve[b] * 0.017453292519943295f;
    float ct = cosf(th), st = sinf(th);
    float Yr = ct*d - st*Z;
    float Zr = st*d + ct*Z + 88.0f;
    float Xs = X + 250.0f;
    float cx = (Xs/5.0f - 50.0f)/100.0f*2.0f;
    float cy = (Yr/5.0f - 50.0f)/100.0f*2.0f;
    float cz = (Zr/5.0f - 16.0f)/48.0f*2.0f;
    float pos[3] = { cx*50.0f+50.0f, cy*50.0f+50.0f, cz*24.0f+24.0f };
    const int gd[3] = {100,100,48};

    int   ip[3][2];
    float w [3][2];
    #pragma unroll
    for (int dd=0; dd<3; dd++) {
        float fl = floorf(pos[dd]);
        #pragma unroll
        for (int ix=0; ix<2; ix++) {
            float pix = fl + (float)ix;
            bool safe = (pix > 0.0f) && (pix < (float)gd[dd]);
            w[dd][ix]  = safe ? (1.0f - fabsf(pos[dd]-pix)) : 0.0f;
            ip[dd][ix] = safe ? (int)pix : 0;
        }
    }

    float fs[16];
    #pragma unroll
    for (int c=0;c<16;c++) {
        const float2* p0 = (const float2*)(ob + (size_t)(4+c)*N_PIX + (size_t)(2*i)*640 + 2*j);
        const float2* p1 = (const float2*)((const float*)p0 + 640);
        float2 a = *p0, bb = *p1;
        fs[c] = (a.x + a.y + bb.x + bb.y) * 0.25f;
    }

    #pragma unroll
    for (int a=0;a<2;a++)
    #pragma unroll
    for (int e=0;e<2;e++) {
        float w01 = w[0][a]*w[1][e];
        if (w01 == 0.0f) continue;
        size_t cell = ((size_t)b*100 + ip[0][a])*100 + ip[1][e];
        #pragma unroll
        for (int f=0;f<2;f++) {
            float ww = w01*w[2][f];
            if (ww == 0.0f) continue;
            int z = ip[2][f];
            atomicAdd(&g_vox0[cell*ZALL + z], ww);
            if (z >= ZLO && z < ZHI) {
                float* p = g_sem + (cell*ZSEM + (z-ZLO))*16;
                red4(p,    fs[0]*ww,  fs[1]*ww,  fs[2]*ww,  fs[3]*ww);
                red4(p+4,  fs[4]*ww,  fs[5]*ww,  fs[6]*ww,  fs[7]*ww);
                red4(p+8,  fs[8]*ww,  fs[9]*ww,  fs[10]*ww, fs[11]*ww);
                red4(p+12, fs[12]*ww, fs[13]*ww, fs[14]*ww, fs[15]*ww);
            }
        }
    }
}

// ---------------- K2a: ch0 projections (map/exp/stair) + re-zero ----------------
__global__ void __launch_bounds__(256) k_proj0() {
    int t = blockIdx.x*blockDim.x + threadIdx.x;
    if (t >= 8*100*100) return;
    int y = t % 100;
    int x = (t/100) % 100;
    int b = t / 10000;
    float4* v = (float4*)(g_vox0 + (size_t)t*ZALL);
    float ah=0.f, allv=0.f, stv=0.f;
    const float4 z4 = make_float4(0.f,0.f,0.f,0.f);
    #pragma unroll
    for (int half=0; half<2; half++) {
        float4 r[6];
        #pragma unroll
        for (int q=0; q<6; q++) r[q] = v[half*6 + q];
        #pragma unroll
        for (int q=0; q<6; q++) v[half*6 + q] = z4;
        #pragma unroll
        for (int q=0; q<6; q++) {
            float vals[4] = {r[q].x, r[q].y, r[q].z, r[q].w};
            #pragma unroll
            for (int k=0;k<4;k++) {
                int z = half*24 + q*4 + k;
                float qq = rintf(vals[k]);
                allv += qq;
                if (z>=ZLO && z<ZHI) ah += qq;
                if (z>=20 && z<25) stv += qq;
            }
        }
    }
    size_t po = (size_t)b*19*10000 + (size_t)y*100 + x;
    g_proj[po]            = fminf(fmaxf(ah,  0.f),1.f);
    g_proj[po +  10000]   = fminf(fmaxf(allv,0.f),1.f);
    g_proj[po + 18*10000] = fminf(fmaxf(stv, 0.f),1.f);
}

// ---------------- K2b: sem projections + re-zero (vectorized, batched) ----------------
__global__ void __launch_bounds__(256) k_projsem() {
    int t = blockIdx.x*blockDim.x + threadIdx.x;
    if (t >= 8*100*100*4) return;
    int g    = t & 3;              // channel group (4 ch each)
    int cell = t >> 2;             // b*10000 + x*100 + y
    int y = cell % 100;
    int x = (cell/100) % 100;
    int b = cell / 10000;
    float4* v = (float4*)(g_sem + (size_t)cell*ZSEM*16) + g;   // stride 4 float4 per z
    float a0=0.f, a1=0.f, a2=0.f, a3=0.f;
    const float4 z4 = make_float4(0.f,0.f,0.f,0.f);
    #pragma unroll
    for (int half=0; half<2; half++) {
        float4 r[11];
        #pragma unroll
        for (int z=0; z<11; z++) r[z] = v[(half*11 + z)*4];
        #pragma unroll
        for (int z=0; z<11; z++) v[(half*11 + z)*4] = z4;
        #pragma unroll
        for (int z=0; z<11; z++) {
            a0 += rintf(r[z].x);
            a1 += rintf(r[z].y);
            a2 += rintf(r[z].z);
            a3 += rintf(r[z].w);
        }
    }
    size_t po = (size_t)b*19*10000 + (size_t)(2 + g*4)*10000 + (size_t)y*100 + x;
    g_proj[po]         = fminf(fmaxf(a0*0.2f, 0.f), 1.f);
    g_proj[po+10000]   = fminf(fmaxf(a1*0.2f, 0.f), 1.f);
    g_proj[po+20000]   = fminf(fmaxf(a2*0.2f, 0.f), 1.f);
    g_proj[po+30000]   = fminf(fmaxf(a3*0.2f, 0.f), 1.f);
}

// ---------------- fused rot-sample helper ----------------
struct Tap { int o0,o1,o2,o3; float w0,w1,w2,w3; };

__device__ __forceinline__ bool rot_taps(float cc, float ss, int ir, int jr, Tap& tp) {
    if (ir < 0 || ir >= 480 || jr < 0 || jr >= 480) return false;
    float gxp = ((float)jr + 0.5f)*(1.0f/240.0f) - 1.0f;
    float gyp = ((float)ir + 0.5f)*(1.0f/240.0f) - 1.0f;
    float fxp = (cc*gxp - ss*gyp + 1.0f)*239.5f;
    float fyp = (ss*gxp + cc*gyp + 1.0f)*239.5f;
    float xf = floorf(fxp), yf = floorf(fyp);
    int xp = (int)xf, yp = (int)yf;
    if (xp < 189 || xp > 289 || yp < 239 || yp > 339) return false;
    float ux1 = fxp - xf, ux0 = 1.0f - ux1;
    float uy1 = fyp - yf, uy0 = 1.0f - uy1;
    int xs0 = xp-190, xs1 = xp-189, ys0 = yp-240, ys1 = yp-239;
    bool vx0 = (xs0>=0 && xs0<100), vx1 = (xs1>=0 && xs1<100);
    bool vy0 = (ys0>=0 && ys0<100), vy1 = (ys1>=0 && ys1<100);
    tp.w0 = (vx0&&vy0) ? ux0*uy0 : 0.0f;
    tp.w1 = (vx1&&vy0) ? ux1*uy0 : 0.0f;
    tp.w2 = (vx0&&vy1) ? ux0*uy1 : 0.0f;
    tp.w3 = (vx1&&vy1) ? ux1*uy1 : 0.0f;
    tp.o0 = (vx0&&vy0) ? ys0*100+xs0 : 0;
    tp.o1 = (vx1&&vy0) ? ys0*100+xs1 : 0;
    tp.o2 = (vx0&&vy1) ? ys1*100+xs0 : 0;
    tp.o3 = (vx1&&vy1) ? ys1*100+xs1 : 0;
    return true;
}

// ---------------- K3: double-bilinear warp -> translated (out_t) + stair scratch ----------------
__global__ void k_warp(float* __restrict__ out_t) {
    int t = blockIdx.x*blockDim.x + threadIdx.x;
    if (t >= 8*NM) return;
    int j = t % 480, i = (t/480) % 480, b = t/NM;
    float cc  = g_par[b*4+0], ss  = g_par[b*4+1];
    float stx = g_par[b*4+2], sty = g_par[b*4+3];

    float gx = ((float)j + 0.5f)*(1.0f/240.0f) - 1.0f + stx;
    float gy = ((float)i + 0.5f)*(1.0f/240.0f) - 1.0f + sty;
    float fx = (gx + 1.0f)*239.5f;
    float fy = (gy + 1.0f)*239.5f;
    float x0f = floorf(fx), y0f = floorf(fy);
    int x0 = (int)x0f, y0 = (int)y0f;
    float wx1 = fx - x0f, wx0 = 1.0f - wx1;
    float wy1 = fy - y0f, wy0 = 1.0f - wy1;

    Tap ct[4]; bool cin[4];
    cin[0] = rot_taps(cc, ss, y0,   x0,   ct[0]);
    cin[1] = rot_taps(cc, ss, y0,   x0+1, ct[1]);
    cin[2] = rot_taps(cc, ss, y0+1, x0,   ct[2]);
    cin[3] = rot_taps(cc, ss, y0+1, x0+1, ct[3]);

    size_t pix = (size_t)i*480 + j;
    size_t ob = (size_t)b*20*NM + pix;

    if (!(cin[0] | cin[1] | cin[2] | cin[3])) {
        #pragma unroll
        for (int c=0;c<20;c++) out_t[ob + (size_t)c*NM] = 0.0f;
        g_stair[(size_t)b*NM + pix] = 0.0f;
        return;
    }

    const float* pb = g_proj + (size_t)b*19*10000;
    float cw[4] = { wx0*wy0, wx1*wy0, wx0*wy1, wx1*wy1 };

    #pragma unroll
    for (int p=0;p<19;p++) {
        const float* pp = pb + p*10000;
        float acc = 0.0f;
        #pragma unroll
        for (int k=0;k<4;k++) {
            if (!cin[k]) continue;
            acc += cw[k]*(ct[k].w0*pp[ct[k].o0] + ct[k].w1*pp[ct[k].o1] +
                          ct[k].w2*pp[ct[k].o2] + ct[k].w3*pp[ct[k].o3]);
        }
        if (p == 0)       out_t[ob]                    = acc;
        else if (p == 1)  out_t[ob + (size_t)NM]       = acc;
        else if (p <= 17) out_t[ob + (size_t)(p+2)*NM] = acc;
        else              g_stair[(size_t)b*NM + pix]  = acc;
    }
    out_t[ob + (size_t)2*NM] = 0.0f;
    out_t[ob + (size_t)3*NM] = 0.0f;
}

// ---------------- K4: maxpool/diff/mask/merge -> map_pred, map_pred_stair ----------------
__global__ void k_merge(const float* __restrict__ maps_last,
                        const float* __restrict__ eve,
                        const float* __restrict__ out_t,
                        float* __restrict__ out_p,
                        float* __restrict__ out_s) {
    int t = blockIdx.x*blockDim.x + threadIdx.x;
    if (t >= 8*NM) return;
    int j = t % 480, i = (t/480) % 480, b = t/NM;
    size_t pix = (size_t)i*480 + j;
    const float* tb = out_t + (size_t)b*20*NM;

    // 3x3 maxpool on translated ch0 (L2-hot from k_warp)
    float t0 = tb[pix];
    float mp = t0;
    #pragma unroll
    for (int di=-1; di<=1; di++) {
        int ii = i + di;
        if (ii < 0 || ii >= 480) continue;
        #pragma unroll
        for (int dj=-1; dj<=1; dj++) {
            if (di==0 && dj==0) continue;
            int jj = j + dj;
            if (jj < 0 || jj >= 480) continue;
            mp = fmaxf(mp, tb[(size_t)ii*480 + jj]);
        }
    }
    float t1 = tb[(size_t)NM + pix];
    bool eve0 = (eve[b] == 0.0f);
    bool dth  = (t1 - mp) > 0.8f;

    float mask = 1.0f;
    if (b == 0) {
        float dy = (float)i - (float)g_sxy[1] + 0.5f;
        float dx = (float)j - (float)g_sxy[0] + 0.5f;
        mask = (dy*dy + dx*dx <= 900.0f) ? 1.0f : 0.0f;
    }
    float ts0 = g_stair[(size_t)b*NM + pix] * mask;
    float ts1 = (b == 0) ? t1*mask : t1;
    bool dsth = (ts1 - ts0) > 0.8f;

    const float* ml = maps_last + (size_t)b*20*NM + pix;
    size_t ob = (size_t)b*20*NM + pix;
    #pragma unroll
    for (int c=0; c<20; c++) {
        float mlv = ml[(size_t)c*NM];
        float tc;
        if (c == 0) tc = t0;
        else if (c == 1) tc = t1;
        else if (c < 4) tc = 0.0f;
        else tc = tb[(size_t)c*NM + pix];
        float m2 = fmaxf(mlv, tc);
        out_p[ob + (size_t)c*NM] = (c==0 && eve0 && dth) ? 0.0f : m2;
        float m3;
        if (c == 0)      m3 = (eve0 && dsth) ? 0.0f : fmaxf(mlv, ts0);
        else if (c == 1) m3 = fmaxf(mlv, ts1);
        else             m3 = m2;
        out_s[ob + (size_t)c*NM] = m3;
    }
}

// ---------------- launch ----------------
extern "C" void kernel_launch(void* const* d_in, const int* in_sizes, int n_in,
                              void* d_out, int out_size) {
    const float* obs        = (const float*)d_in[0];
    const float* pose_obs   = (const float*)d_in[1];
    const float* maps_last  = (const float*)d_in[2];
    const float* poses_last = (const float*)d_in[3];
    const float* eve        = (const float*)d_in[4];
    float* out = (float*)d_out;

    float camf = (float)(320.0 / tan(39.5 * 3.14159265358979323846 / 180.0));

    k_pose   <<<1, 8>>>(pose_obs, poses_last, out + (size_t)3*N1);
    k_splat  <<<(8*240*320 + 255)/256, 256>>>(obs, eve, camf);
    k_proj0  <<<(8*100*100 + 255)/256, 256>>>();
    k_projsem<<<(8*100*100*4 + 255)/256, 256>>>();
    k_warp   <<<(8*NM + 255)/256, 256>>>(out);
    k_merge  <<<(8*NM + 255)/256, 256>>>(maps_last, eve, out,
                                         out + (size_t)N1, out + (size_t)2*N1);
}

// round 5
// speedup vs baseline: 2.1429x; 1.0202x over previous
#include <cuda_runtime.h>
#include <math.h>
#include <stdint.h>

// ---------------- constants ----------------
#define N_PIX (480*640)
#define NM    (480*480)          // one 480x480 plane
#define N1    (8*20*480*480)     // one full (bs,20,480,480) tensor
#define ZALL  48
#define ZLO   13                 // ah range [13,35)
#define ZHI   35
#define ZSEM  22                 // ZHI-ZLO

// ---------------- device scratch ----------------
__device__ float g_vox0[8*100*100*ZALL];        // [b][x][y][z]        15MB (ch0 counts)
__device__ float g_sem [8*100*100*ZSEM*16];     // [b][x][y][zr][ch]  113MB (sem feats)
__device__ float g_proj[8*19*100*100];          // [b][plane][y][x]; 0=map 1=exp 2..17=sem 18=stair
__device__ float g_stair[8*NM];                 // translated stair ch0 (unmasked)
__device__ float g_par[32];                     // per b: cos, sin, stx, sty
__device__ int   g_sxy[2];                      // stair circle center (x, y), batch 0

// ---------------- vector reduction helper ----------------
__device__ __forceinline__ void red4(float* p, float a, float b, float c, float d) {
    asm volatile("red.global.add.v4.f32 [%0], {%1,%2,%3,%4};"
                 :: "l"(p), "f"(a), "f"(b), "f"(c), "f"(d) : "memory");
}

// ---------------- K0: poses + transform params ----------------
__global__ void k_pose(const float* __restrict__ pose_obs,
                       const float* __restrict__ poses_last,
                       float* __restrict__ out_pose) {
    int b = threadIdx.x;
    if (b >= 8) return;
    const float DEGf = 57.29577951308232f;
    float tr = poses_last[b*3+2] / DEGf;
    float s = sinf(tr), c = cosf(tr);
    float ny = poses_last[b*3+1] + pose_obs[b*3+0]*s + pose_obs[b*3+1]*c;
    float nx = poses_last[b*3+0] + pose_obs[b*3+0]*c - pose_obs[b*3+1]*s;
    float no = poses_last[b*3+2] + pose_obs[b*3+2]*DEGf;
    no = fmodf(no - 180.0f, 360.0f) + 180.0f;
    no = fmodf(no + 180.0f, 360.0f) - 180.0f;
    out_pose[b*3+0] = nx; out_pose[b*3+1] = ny; out_pose[b*3+2] = no;

    float stx = -(nx*100.0f/5.0f - 240.0f)/240.0f;
    float sty = -(ny*100.0f/5.0f - 240.0f)/240.0f;
    float st_t = (90.0f - no) * 0.017453292519943295f;
    g_par[b*4+0] = cosf(st_t);
    g_par[b*4+1] = sinf(st_t);
    g_par[b*4+2] = stx;
    g_par[b*4+3] = sty;
    if (b == 0) {
        int sy = (int)(ny*100.0f/5.0f); sy = min(max(sy,30),449);
        int sx = (int)(nx*100.0f/5.0f); sx = min(max(sx,30),449);
        g_sxy[0] = sx; g_sxy[1] = sy;
    }
}

// ---------------- K1: trilinear splat ----------------
__global__ void k_splat(const float* __restrict__ obs,
                        const float* __restrict__ eve, float camf) {
    int t = blockIdx.x*blockDim.x + threadIdx.x;
    if (t >= 8*240*320) return;
    int j = t % 320;
    int i = (t/320) % 240;
    int b = t / (320*240);
    const float* ob = obs + (size_t)b*20*N_PIX;

    float d = ob[(size_t)3*N_PIX + (size_t)(2*i)*640 + 2*j];
    float X = ((float)(2*j) - 319.5f) * d / camf;
    float Z = ((float)(479 - 2*i) - 239.5f) * d / camf;
    float th = eve[b] * 0.017453292519943295f;
    float ct = cosf(th), st = sinf(th);
    float Yr = ct*d - st*Z;
    float Zr = st*d + ct*Z + 88.0f;
    float Xs = X + 250.0f;
    float cx = (Xs/5.0f - 50.0f)/100.0f*2.0f;
    float cy = (Yr/5.0f - 50.0f)/100.0f*2.0f;
    float cz = (Zr/5.0f - 16.0f)/48.0f*2.0f;
    float pos[3] = { cx*50.0f+50.0f, cy*50.0f+50.0f, cz*24.0f+24.0f };
    const int gd[3] = {100,100,48};

    int   ip[3][2];
    float w [3][2];
    #pragma unroll
    for (int dd=0; dd<3; dd++) {
        float fl = floorf(pos[dd]);
        #pragma unroll
        for (int ix=0; ix<2; ix++) {
            float pix = fl + (float)ix;
            bool safe = (pix > 0.0f) && (pix < (float)gd[dd]);
            w[dd][ix]  = safe ? (1.0f - fabsf(pos[dd]-pix)) : 0.0f;
            ip[dd][ix] = safe ? (int)pix : 0;
        }
    }

    float fs[16];
    #pragma unroll
    for (int c=0;c<16;c++) {
        const float2* p0 = (const float2*)(ob + (size_t)(4+c)*N_PIX + (size_t)(2*i)*640 + 2*j);
        const float2* p1 = (const float2*)((const float*)p0 + 640);
        float2 a = *p0, bb = *p1;
        fs[c] = (a.x + a.y + bb.x + bb.y) * 0.25f;
    }

    #pragma unroll
    for (int a=0;a<2;a++)
    #pragma unroll
    for (int e=0;e<2;e++) {
        float w01 = w[0][a]*w[1][e];
        if (w01 == 0.0f) continue;
        size_t cell = ((size_t)b*100 + ip[0][a])*100 + ip[1][e];
        #pragma unroll
        for (int f=0;f<2;f++) {
            float ww = w01*w[2][f];
            if (ww == 0.0f) continue;
            int z = ip[2][f];
            atomicAdd(&g_vox0[cell*ZALL + z], ww);
            if (z >= ZLO && z < ZHI) {
                float* p = g_sem + (cell*ZSEM + (z-ZLO))*16;
                red4(p,    fs[0]*ww,  fs[1]*ww,  fs[2]*ww,  fs[3]*ww);
                red4(p+4,  fs[4]*ww,  fs[5]*ww,  fs[6]*ww,  fs[7]*ww);
                red4(p+8,  fs[8]*ww,  fs[9]*ww,  fs[10]*ww, fs[11]*ww);
                red4(p+12, fs[12]*ww, fs[13]*ww, fs[14]*ww, fs[15]*ww);
            }
        }
    }
}

// ---------------- K2a: ch0 projections (map/exp/stair) + re-zero ----------------
__global__ void __launch_bounds__(256) k_proj0() {
    int t = blockIdx.x*blockDim.x + threadIdx.x;
    if (t >= 8*100*100) return;
    int y = t % 100;
    int x = (t/100) % 100;
    int b = t / 10000;
    float4* v = (float4*)(g_vox0 + (size_t)t*ZALL);
    float ah=0.f, allv=0.f, stv=0.f;
    const float4 z4 = make_float4(0.f,0.f,0.f,0.f);
    #pragma unroll
    for (int half=0; half<2; half++) {
        float4 r[6];
        #pragma unroll
        for (int q=0; q<6; q++) r[q] = v[half*6 + q];
        #pragma unroll
        for (int q=0; q<6; q++) v[half*6 + q] = z4;
        #pragma unroll
        for (int q=0; q<6; q++) {
            float vals[4] = {r[q].x, r[q].y, r[q].z, r[q].w};
            #pragma unroll
            for (int k=0;k<4;k++) {
                int z = half*24 + q*4 + k;
                float qq = rintf(vals[k]);
                allv += qq;
                if (z>=ZLO && z<ZHI) ah += qq;
                if (z>=20 && z<25) stv += qq;
            }
        }
    }
    size_t po = (size_t)b*19*10000 + (size_t)y*100 + x;
    g_proj[po]            = fminf(fmaxf(ah,  0.f),1.f);
    g_proj[po +  10000]   = fminf(fmaxf(allv,0.f),1.f);
    g_proj[po + 18*10000] = fminf(fmaxf(stv, 0.f),1.f);
}

// ---------------- K2b: sem projections + re-zero (vectorized, batched) ----------------
__global__ void __launch_bounds__(256) k_projsem() {
    int t = blockIdx.x*blockDim.x + threadIdx.x;
    if (t >= 8*100*100*4) return;
    int g    = t & 3;              // channel group (4 ch each)
    int cell = t >> 2;             // b*10000 + x*100 + y
    int y = cell % 100;
    int x = (cell/100) % 100;
    int b = cell / 10000;
    float4* v = (float4*)(g_sem + (size_t)cell*ZSEM*16) + g;   // stride 4 float4 per z
    float a0=0.f, a1=0.f, a2=0.f, a3=0.f;
    const float4 z4 = make_float4(0.f,0.f,0.f,0.f);
    #pragma unroll
    for (int half=0; half<2; half++) {
        float4 r[11];
        #pragma unroll
        for (int z=0; z<11; z++) r[z] = v[(half*11 + z)*4];
        #pragma unroll
        for (int z=0; z<11; z++) v[(half*11 + z)*4] = z4;
        #pragma unroll
        for (int z=0; z<11; z++) {
            a0 += rintf(r[z].x);
            a1 += rintf(r[z].y);
            a2 += rintf(r[z].z);
            a3 += rintf(r[z].w);
        }
    }
    size_t po = (size_t)b*19*10000 + (size_t)(2 + g*4)*10000 + (size_t)y*100 + x;
    g_proj[po]         = fminf(fmaxf(a0*0.2f, 0.f), 1.f);
    g_proj[po+10000]   = fminf(fmaxf(a1*0.2f, 0.f), 1.f);
    g_proj[po+20000]   = fminf(fmaxf(a2*0.2f, 0.f), 1.f);
    g_proj[po+30000]   = fminf(fmaxf(a3*0.2f, 0.f), 1.f);
}

// ---------------- fused rot-sample helper ----------------
struct Tap { int o0,o1,o2,o3; float w0,w1,w2,w3; };

__device__ __forceinline__ bool rot_taps(float cc, float ss, int ir, int jr, Tap& tp) {
    if (ir < 0 || ir >= 480 || jr < 0 || jr >= 480) return false;
    float gxp = ((float)jr + 0.5f)*(1.0f/240.0f) - 1.0f;
    float gyp = ((float)ir + 0.5f)*(1.0f/240.0f) - 1.0f;
    float fxp = (cc*gxp - ss*gyp + 1.0f)*239.5f;
    float fyp = (ss*gxp + cc*gyp + 1.0f)*239.5f;
    float xf = floorf(fxp), yf = floorf(fyp);
    int xp = (int)xf, yp = (int)yf;
    if (xp < 189 || xp > 289 || yp < 239 || yp > 339) return false;
    float ux1 = fxp - xf, ux0 = 1.0f - ux1;
    float uy1 = fyp - yf, uy0 = 1.0f - uy1;
    int xs0 = xp-190, xs1 = xp-189, ys0 = yp-240, ys1 = yp-239;
    bool vx0 = (xs0>=0 && xs0<100), vx1 = (xs1>=0 && xs1<100);
    bool vy0 = (ys0>=0 && ys0<100), vy1 = (ys1>=0 && ys1<100);
    tp.w0 = (vx0&&vy0) ? ux0*uy0 : 0.0f;
    tp.w1 = (vx1&&vy0) ? ux1*uy0 : 0.0f;
    tp.w2 = (vx0&&vy1) ? ux0*uy1 : 0.0f;
    tp.w3 = (vx1&&vy1) ? ux1*uy1 : 0.0f;
    tp.o0 = (vx0&&vy0) ? ys0*100+xs0 : 0;
    tp.o1 = (vx1&&vy0) ? ys0*100+xs1 : 0;
    tp.o2 = (vx0&&vy1) ? ys1*100+xs0 : 0;
    tp.o3 = (vx1&&vy1) ? ys1*100+xs1 : 0;
    return true;
}

// ---------------- K3: warp + merge for channels 2..19, out_t all channels ----------------
__global__ void k_warp(const float* __restrict__ maps_last,
                       float* __restrict__ out_t,
                       float* __restrict__ out_p,
                       float* __restrict__ out_s) {
    int t = blockIdx.x*blockDim.x + threadIdx.x;
    if (t >= 8*NM) return;
    int j = t % 480, i = (t/480) % 480, b = t/NM;
    float cc  = g_par[b*4+0], ss  = g_par[b*4+1];
    float stx = g_par[b*4+2], sty = g_par[b*4+3];

    float gx = ((float)j + 0.5f)*(1.0f/240.0f) - 1.0f + stx;
    float gy = ((float)i + 0.5f)*(1.0f/240.0f) - 1.0f + sty;
    float fx = (gx + 1.0f)*239.5f;
    float fy = (gy + 1.0f)*239.5f;
    float x0f = floorf(fx), y0f = floorf(fy);
    int x0 = (int)x0f, y0 = (int)y0f;
    float wx1 = fx - x0f, wx0 = 1.0f - wx1;
    float wy1 = fy - y0f, wy0 = 1.0f - wy1;

    Tap ct[4]; bool cin[4];
    cin[0] = rot_taps(cc, ss, y0,   x0,   ct[0]);
    cin[1] = rot_taps(cc, ss, y0,   x0+1, ct[1]);
    cin[2] = rot_taps(cc, ss, y0+1, x0,   ct[2]);
    cin[3] = rot_taps(cc, ss, y0+1, x0+1, ct[3]);

    size_t pix = (size_t)i*480 + j;
    size_t ob = (size_t)b*20*NM + pix;
    const float* ml = maps_last + ob;

    if (!(cin[0] | cin[1] | cin[2] | cin[3])) {
        out_t[ob]               = 0.0f;
        out_t[ob + (size_t)NM]  = 0.0f;
        g_stair[(size_t)b*NM + pix] = 0.0f;
        #pragma unroll
        for (int c=2;c<20;c++) {
            out_t[ob + (size_t)c*NM] = 0.0f;
            float m = fmaxf(ml[(size_t)c*NM], 0.0f);
            out_p[ob + (size_t)c*NM] = m;
            out_s[ob + (size_t)c*NM] = m;
        }
        return;
    }

    const float* pb = g_proj + (size_t)b*19*10000;
    float cw[4] = { wx0*wy0, wx1*wy0, wx0*wy1, wx1*wy1 };

    #pragma unroll
    for (int p=0;p<19;p++) {
        const float* pp = pb + p*10000;
        float acc = 0.0f;
        #pragma unroll
        for (int k=0;k<4;k++) {
            if (!cin[k]) continue;
            acc += cw[k]*(ct[k].w0*pp[ct[k].o0] + ct[k].w1*pp[ct[k].o1] +
                          ct[k].w2*pp[ct[k].o2] + ct[k].w3*pp[ct[k].o3]);
        }
        if (p == 0)       out_t[ob]               = acc;
        else if (p == 1)  out_t[ob + (size_t)NM]  = acc;
        else if (p <= 17) {
            int c = p + 2;
            out_t[ob + (size_t)c*NM] = acc;
            float m = fmaxf(ml[(size_t)c*NM], acc);
            out_p[ob + (size_t)c*NM] = m;
            out_s[ob + (size_t)c*NM] = m;
        }
        else              g_stair[(size_t)b*NM + pix] = acc;
    }
    // channels 2,3 are always zero in agent_view
    #pragma unroll
    for (int c=2;c<4;c++) {
        out_t[ob + (size_t)c*NM] = 0.0f;
        float m = fmaxf(ml[(size_t)c*NM], 0.0f);
        out_p[ob + (size_t)c*NM] = m;
        out_s[ob + (size_t)c*NM] = m;
    }
}

// ---------------- K4: channels 0,1 -> maxpool/diff/mask/merge ----------------
__global__ void k_merge(const float* __restrict__ maps_last,
                        const float* __restrict__ eve,
                        const float* __restrict__ out_t,
                        float* __restrict__ out_p,
                        float* __restrict__ out_s) {
    int t = blockIdx.x*blockDim.x + threadIdx.x;
    if (t >= 8*NM) return;
    int j = t % 480, i = (t/480) % 480, b = t/NM;
    size_t pix = (size_t)i*480 + j;
    const float* tb = out_t + (size_t)b*20*NM;

    // 3x3 maxpool on translated ch0 (L2-hot from k_warp)
    float t0 = tb[pix];
    float mp = t0;
    #pragma unroll
    for (int di=-1; di<=1; di++) {
        int ii = i + di;
        if (ii < 0 || ii >= 480) continue;
        #pragma unroll
        for (int dj=-1; dj<=1; dj++) {
            if (di==0 && dj==0) continue;
            int jj = j + dj;
            if (jj < 0 || jj >= 480) continue;
            mp = fmaxf(mp, tb[(size_t)ii*480 + jj]);
        }
    }
    float t1 = tb[(size_t)NM + pix];
    bool eve0 = (eve[b] == 0.0f);
    bool dth  = (t1 - mp) > 0.8f;

    float mask = 1.0f;
    if (b == 0) {
        float dy = (float)i - (float)g_sxy[1] + 0.5f;
        float dx = (float)j - (float)g_sxy[0] + 0.5f;
        mask = (dy*dy + dx*dx <= 900.0f) ? 1.0f : 0.0f;
    }
    float ts0 = g_stair[(size_t)b*NM + pix] * mask;
    float ts1 = (b == 0) ? t1*mask : t1;
    bool dsth = (ts1 - ts0) > 0.8f;

    size_t ob = (size_t)b*20*NM + pix;
    float ml0 = maps_last[ob];
    float ml1 = maps_last[ob + (size_t)NM];

    float m20 = fmaxf(ml0, t0);
    out_p[ob]              = (eve0 && dth) ? 0.0f : m20;
    out_p[ob + (size_t)NM] = fmaxf(ml1, t1);
    out_s[ob]              = (eve0 && dsth) ? 0.0f : fmaxf(ml0, ts0);
    out_s[ob + (size_t)NM] = fmaxf(ml1, ts1);
}

// ---------------- launch ----------------
extern "C" void kernel_launch(void* const* d_in, const int* in_sizes, int n_in,
                              void* d_out, int out_size) {
    const float* obs        = (const float*)d_in[0];
    const float* pose_obs   = (const float*)d_in[1];
    const float* maps_last  = (const float*)d_in[2];
    const float* poses_last = (const float*)d_in[3];
    const float* eve        = (const float*)d_in[4];
    float* out = (float*)d_out;

    float camf = (float)(320.0 / tan(39.5 * 3.14159265358979323846 / 180.0));

    k_pose   <<<1, 8>>>(pose_obs, poses_last, out + (size_t)3*N1);
    k_splat  <<<(8*240*320 + 255)/256, 256>>>(obs, eve, camf);
    k_proj0  <<<(8*100*100 + 255)/256, 256>>>();
    k_projsem<<<(8*100*100*4 + 255)/256, 256>>>();
    k_warp   <<<(8*NM + 255)/256, 256>>>(maps_last, out,
                                         out + (size_t)N1, out + (size_t)2*N1);
    k_merge  <<<(8*NM + 255)/256, 256>>>(maps_last, eve, out,
                                         out + (size_t)N1, out + (size_t)2*N1);
}